// round 15
// baseline (speedup 1.0000x reference)
#include <cuda_runtime.h>
#include <stdint.h>

// out[j] = (|bits[j % 4096]| > 0.5) ? 1.0f : 0.0f for all j in [0, 48*2^20).
// 192 MiB output = 16 KB-periodic pattern. Build the 16 KB pattern in SMEM,
// then blast it to GMEM with TMA bulk stores (SMEM->L2->HBM, bypasses L1).
//
// ROOFLINE: all store-path variants converge on ~31.3-31.9us = 201 MB at
// ~6.4 TB/s = the full-chip LTS write-ingress cap (path-independent). This
// round: contiguous per-block address stripes (DRAM row locality for the L2
// drain) + issuer warps excluded from the pattern-build loop (shorter ramp).

static constexpr int THREADS     = 512;
static constexpr int BLOCKS      = 152;              // one block per SM
static constexpr int PAT4        = 1024;             // 16 KB pattern in float4s
static constexpr int CHUNK_BYTES = PAT4 * 16;        // 16 KB

__device__ __forceinline__ uint32_t smem_u32(const void* p) {
    uint32_t a;
    asm("{ .reg .u64 t; cvta.to.shared.u64 t, %1; cvt.u32.u64 %0, t; }"
        : "=r"(a) : "l"(p));
    return a;
}

__global__ __launch_bounds__(THREADS, 1)
void fill_periodic_tma_kernel(const float* __restrict__ bits,
                              char* __restrict__ out,
                              long long n_chunks)
{
    __shared__ float4 pat[PAT4];   // 16 KB

    const int wid = threadIdx.x >> 5;

    // Warps 2..15 (448 threads) build the pattern; issuer warps 0/1 go
    // straight to the barrier so they start TMA issue with zero LDG latency
    // in their own path.
    if (wid >= 2) {
        const float4* bits4 = reinterpret_cast<const float4*>(bits);
        for (int i = threadIdx.x - 64; i < PAT4; i += THREADS - 64) {
            float4 b = bits4[i];
            float4 v;
            v.x = (fabsf(b.x) > 0.5f) ? 1.0f : 0.0f;
            v.y = (fabsf(b.y) > 0.5f) ? 1.0f : 0.0f;
            v.z = (fabsf(b.z) > 0.5f) ? 1.0f : 0.0f;
            v.w = (fabsf(b.w) > 0.5f) ? 1.0f : 0.0f;
            pat[i] = v;
        }
    }
    __syncthreads();
    // Order generic-proxy SMEM writes before async-proxy (TMA) reads.
    asm volatile("fence.proxy.async.shared::cta;" ::: "memory");

    // Contiguous stripes: block b owns chunks [b*cpb, (b+1)*cpb); each of the
    // two issuer warps takes a contiguous half of that stripe.
    if ((threadIdx.x & 31) == 0 && wid < 2) {
        uint32_t saddr = smem_u32(pat);
        uint64_t pol;
        asm("createpolicy.fractional.L2::evict_first.b64 %0, 1.0;" : "=l"(pol));

        const long long cpb   = (n_chunks + gridDim.x - 1) / gridDim.x;  // 81
        const long long half  = (cpb + 1) >> 1;
        long long begin = (long long)blockIdx.x * cpb + (long long)wid * half;
        long long end   = (long long)blockIdx.x * cpb
                        + ((wid == 0) ? half : cpb);
        if (end > n_chunks) end = n_chunks;

        for (long long c = begin; c < end; c++) {
            char* g = out + c * (long long)CHUNK_BYTES;
            asm volatile(
                "cp.async.bulk.global.shared::cta.bulk_group.L2::cache_hint"
                " [%0], [%1], %2, %3;"
                :: "l"(g), "r"(saddr), "n"(CHUNK_BYTES), "l"(pol) : "memory");
        }
        asm volatile("cp.async.bulk.commit_group;" ::: "memory");
        asm volatile("cp.async.bulk.wait_group 0;" ::: "memory");
    }
}

extern "C" void kernel_launch(void* const* d_in, const int* in_sizes, int n_in,
                              void* d_out, int out_size)
{
    const float* bits = (const float*)d_in[0];
    long long total_bytes = (long long)out_size * 4;      // 192 MiB
    long long n_chunks = total_bytes / CHUNK_BYTES;       // 12288

    fill_periodic_tma_kernel<<<BLOCKS, THREADS>>>(bits, (char*)d_out, n_chunks);
}

// round 17
// speedup vs baseline: 1.0378x; 1.0378x over previous
#include <cuda_runtime.h>
#include <stdint.h>

// out[j] = (|bits[j % 4096]| > 0.5) ? 1.0f : 0.0f for all j in [0, 48*2^20).
// 192 MiB output = 16 KB-periodic pattern. Build the 16 KB pattern in SMEM,
// then blast it to GMEM with TMA bulk stores (SMEM->L2->HBM, bypasses L1).
//
// ROOFLINE (measured over 7 structural variants): 201 MB ingress / ~31.3us
// = ~6.4 TB/s = the full-chip LTS write-ingress cap (path-independent,
// ~6300 B/cyc). INTERLEAVED chunk->block mapping beats contiguous stripes
// (R14: +0.5us) because consecutive bulk stores 2.4 MB apart keep all LTS
// partitions uniformly loaded. Two issuer warps halve the serial issue ramp;
// evict_first keeps the stream FIFO-like in L2 for the DRAM drain.

static constexpr int THREADS     = 512;
static constexpr int BLOCKS      = 152;              // one block per SM
static constexpr int PAT4        = 1024;             // 16 KB pattern in float4s
static constexpr int CHUNK_BYTES = PAT4 * 16;        // 16 KB

__device__ __forceinline__ uint32_t smem_u32(const void* p) {
    uint32_t a;
    asm("{ .reg .u64 t; cvta.to.shared.u64 t, %1; cvt.u32.u64 %0, t; }"
        : "=r"(a) : "l"(p));
    return a;
}

__global__ __launch_bounds__(THREADS, 1)
void fill_periodic_tma_kernel(const float* __restrict__ bits,
                              char* __restrict__ out,
                              long long n_chunks)
{
    __shared__ float4 pat[PAT4];   // 16 KB

    // Build the pattern (2 iterations per thread, all 16 warps).
    const float4* bits4 = reinterpret_cast<const float4*>(bits);
    for (int i = threadIdx.x; i < PAT4; i += THREADS) {
        float4 b = bits4[i];
        float4 v;
        v.x = (fabsf(b.x) > 0.5f) ? 1.0f : 0.0f;
        v.y = (fabsf(b.y) > 0.5f) ? 1.0f : 0.0f;
        v.z = (fabsf(b.z) > 0.5f) ? 1.0f : 0.0f;
        v.w = (fabsf(b.w) > 0.5f) ? 1.0f : 0.0f;
        pat[i] = v;
    }
    __syncthreads();
    // Order generic-proxy SMEM writes before async-proxy (TMA) reads.
    asm volatile("fence.proxy.async.shared::cta;" ::: "memory");

    // Two issuing threads per block (lane 0 of warps 0 and 1); interleaved
    // chunk mapping: consecutive bulk stores land 152*16KB = 2.4 MB apart,
    // keeping the LTS partitions uniformly loaded chip-wide.
    const int wid = threadIdx.x >> 5;
    if ((threadIdx.x & 31) == 0 && wid < 2) {
        uint32_t saddr = smem_u32(pat);
        uint64_t pol;
        asm("createpolicy.fractional.L2::evict_first.b64 %0, 1.0;" : "=l"(pol));

        const long long step = 2LL * gridDim.x;
        for (long long c = blockIdx.x + (long long)wid * gridDim.x;
             c < n_chunks; c += step) {
            char* g = out + c * (long long)CHUNK_BYTES;
            asm volatile(
                "cp.async.bulk.global.shared::cta.bulk_group.L2::cache_hint"
                " [%0], [%1], %2, %3;"
                :: "l"(g), "r"(saddr), "n"(CHUNK_BYTES), "l"(pol) : "memory");
        }
        asm volatile("cp.async.bulk.commit_group;" ::: "memory");
        asm volatile("cp.async.bulk.wait_group 0;" ::: "memory");
    }
}

extern "C" void kernel_launch(void* const* d_in, const int* in_sizes, int n_in,
                              void* d_out, int out_size)
{
    const float* bits = (const float*)d_in[0];
    long long total_bytes = (long long)out_size * 4;      // 192 MiB
    long long n_chunks = total_bytes / CHUNK_BYTES;       // 12288

    fill_periodic_tma_kernel<<<BLOCKS, THREADS>>>(bits, (char*)d_out, n_chunks);
}